// round 1
// baseline (speedup 1.0000x reference)
#include <cuda_runtime.h>
#include <cstdint>

// FioraModel double_softmax:
//   Per graph g (256 contiguous flat edge values v[0..255], scalar gv):
//     m     = max(max_j v[j], gv)
//     e_j   = exp(v[j]-m),  e_g = exp(gv-m)
//     denom = sum_j e_j + 2*e_g
//     out[258*g + j]        = 2*e_j / denom      (j = 0..255)
//     out[258*g + 256/257]  = 2*e_g / denom
//
// One warp per graph: 256 floats = 2 x float4 per lane. Warp-shuffle
// reductions for max and sum. float2 stores (258*4 = 1032 bytes per block:
// 8B-aligned, not 16B-aligned).

static constexpr int VALS_PER_GRAPH = 256;   // EPG * D
static constexpr int OUT_PER_GRAPH  = 258;
static constexpr unsigned FULL = 0xffffffffu;

__global__ __launch_bounds__(256, 8)
void fiora_double_softmax_kernel(const float4* __restrict__ ev4,
                                 const float*  __restrict__ gv,
                                 float*        __restrict__ out,
                                 int G)
{
    const int warp = (blockIdx.x * blockDim.x + threadIdx.x) >> 5;
    const int lane = threadIdx.x & 31;
    if (warp >= G) return;

    // ---- load: 64 float4 per graph; lane gets #lane and #(lane+32) ----
    const float4* base = ev4 + (size_t)warp * 64;
    float4 a = base[lane];
    float4 b = base[lane + 32];
    float  g = gv[warp];                 // uniform address -> broadcast load

    // ---- max reduction (includes gv) ----
    float m = fmaxf(fmaxf(fmaxf(a.x, a.y), fmaxf(a.z, a.w)),
                    fmaxf(fmaxf(b.x, b.y), fmaxf(b.z, b.w)));
    m = fmaxf(m, g);
    #pragma unroll
    for (int o = 16; o > 0; o >>= 1)
        m = fmaxf(m, __shfl_xor_sync(FULL, m, o));

    // ---- exp + sum reduction ----
    float e0 = __expf(a.x - m), e1 = __expf(a.y - m);
    float e2 = __expf(a.z - m), e3 = __expf(a.w - m);
    float e4 = __expf(b.x - m), e5 = __expf(b.y - m);
    float e6 = __expf(b.z - m), e7 = __expf(b.w - m);

    float s = ((e0 + e1) + (e2 + e3)) + ((e4 + e5) + (e6 + e7));
    #pragma unroll
    for (int o = 16; o > 0; o >>= 1)
        s += __shfl_xor_sync(FULL, s, o);

    float eg    = __expf(g - m);
    float denom = s + 2.0f * eg;
    float inv   = __fdividef(2.0f, denom);   // scale = 2/denom

    // ---- store: 258-float block at out + 258*g, via float2 ----
    float2* ob = reinterpret_cast<float2*>(out + (size_t)warp * OUT_PER_GRAPH);

    ob[2 * lane + 0]        = make_float2(e0 * inv, e1 * inv);
    ob[2 * lane + 1]        = make_float2(e2 * inv, e3 * inv);
    ob[2 * (lane + 32) + 0] = make_float2(e4 * inv, e5 * inv);
    ob[2 * (lane + 32) + 1] = make_float2(e6 * inv, e7 * inv);

    if (lane == 0) {
        float go = eg * inv;
        ob[VALS_PER_GRAPH / 2] = make_float2(go, go);   // out[256], out[257]
    }
}

extern "C" void kernel_launch(void* const* d_in, const int* in_sizes, int n_in,
                              void* d_out, int out_size)
{
    const float* edge_values  = (const float*)d_in[0];   // [G*EPG, D] fp32
    const float* graph_values = (const float*)d_in[1];   // [G, 1]     fp32
    // d_in[2] (batch) / d_in[3] (edge_index0) are not needed: the batching
    // invariant makes seg[i] = i / 256 and the output layout blockwise.

    const int G = in_sizes[1];           // graph_values has G elements

    const int warps_per_block = 8;       // 256 threads
    const int blocks = (G + warps_per_block - 1) / warps_per_block;

    fiora_double_softmax_kernel<<<blocks, 256>>>(
        (const float4*)edge_values, graph_values, (float*)d_out, G);
}